// round 5
// baseline (speedup 1.0000x reference)
#include <cuda_runtime.h>
#include <cuda_bf16.h>
#include <math.h>
#include <stdint.h>

#define D_MODEL 1024
#define D_FF    4096
#define N_EXP   8
#define T_TOK   4096
#define XG_ROWS 9216
#define MAX_TILES 72

// ---- scratch (__device__ globals; no cudaMalloc allowed) --------------------
__device__ int      g_count[N_EXP];
__device__ int      g_off[N_EXP + 1];
__device__ int      g_rows[N_EXP * T_TOK];
__device__ float    g_gate[N_EXP * T_TOK];
__device__ int      g_tileE[MAX_TILES];
__device__ int      g_tileM[MAX_TILES];
__device__ int      g_ntiles;
__device__ int      g_stok[XG_ROWS];
__device__ float    g_sgate[XG_ROWS];
__device__ float    g_sx[XG_ROWS];                 // per-row x scale
__device__ unsigned g_cm1[N_EXP * D_FF];           // colmax |W1| per (e,n)
__device__ unsigned g_cm2[N_EXP * D_MODEL];        // colmax |W2| per (e,n)

__device__ int8_t g_X1[(size_t)XG_ROWS * D_MODEL];
__device__ int8_t g_X2[(size_t)XG_ROWS * D_MODEL];
__device__ int8_t g_W1T1[(size_t)N_EXP * D_FF * D_MODEL];
__device__ int8_t g_W1T2[(size_t)N_EXP * D_FF * D_MODEL];
__device__ int8_t g_W2T1[(size_t)N_EXP * D_MODEL * D_FF];
__device__ int8_t g_W2T2[(size_t)N_EXP * D_MODEL * D_FF];
__device__ int8_t g_H1[(size_t)XG_ROWS * D_FF];
__device__ int8_t g_H2[(size_t)XG_ROWS * D_FF];

// H fixed scale: h in [0, ~5.9] whp; first digit scale S_H = 8/127
#define S_H      (8.0f / 127.0f)
#define INV_S_H  (127.0f / 8.0f)
#define RDIG     254.0f      // residual digit base: res in [-s/2, s/2] -> +-127

// ---- helpers ----------------------------------------------------------------
#define SWZ(o) ((o) ^ (((o) >> 3) & 0x70))

__device__ __forceinline__ uint32_t smem_u32(const void* p) {
    uint32_t a;
    asm("{ .reg .u64 t; cvta.to.shared.u64 t, %1; cvt.u32.u64 %0, t; }"
        : "=r"(a) : "l"(p));
    return a;
}
__device__ __forceinline__ void cp16(uint32_t dst, const void* src) {
    asm volatile("cp.async.cg.shared.global [%0], [%1], 16;"
                 :: "r"(dst), "l"(src) : "memory");
}
__device__ __forceinline__ void ldsm4(uint32_t* r, uint32_t addr) {
    asm volatile("ldmatrix.sync.aligned.m8n8.x4.shared.b16 {%0,%1,%2,%3}, [%4];"
                 : "=r"(r[0]), "=r"(r[1]), "=r"(r[2]), "=r"(r[3]) : "r"(addr));
}
__device__ __forceinline__ void mma_s8(int* d, const uint32_t* a, const uint32_t* b) {
    asm volatile("mma.sync.aligned.m16n8k32.row.col.s32.s8.s8.s32 "
        "{%0,%1,%2,%3}, {%4,%5,%6,%7}, {%8,%9}, {%0,%1,%2,%3};"
        : "+r"(d[0]), "+r"(d[1]), "+r"(d[2]), "+r"(d[3])
        : "r"(a[0]), "r"(a[1]), "r"(a[2]), "r"(a[3]), "r"(b[0]), "r"(b[1]));
}
__device__ __forceinline__ int8_t clamp8(float v) {
    return (int8_t)fmaxf(-127.f, fminf(127.f, v));
}

// ---- routing ----------------------------------------------------------------
__global__ void zero_counts_kernel() {
    if (threadIdx.x < N_EXP) g_count[threadIdx.x] = 0;
}

__global__ void router_kernel(const float* __restrict__ x,
                              const float* __restrict__ Wr) {
    int tok  = (blockIdx.x * blockDim.x + threadIdx.x) >> 5;
    int lane = threadIdx.x & 31;
    if (tok >= T_TOK) return;
    const float* xr = x + (size_t)tok * D_MODEL;
    float acc[N_EXP];
#pragma unroll
    for (int e = 0; e < N_EXP; e++) acc[e] = 0.f;
    for (int d = lane; d < D_MODEL; d += 32) {
        float xv = xr[d];
        float4 w0 = *(const float4*)(Wr + (size_t)d * N_EXP);
        float4 w1 = *(const float4*)(Wr + (size_t)d * N_EXP + 4);
        acc[0] += xv * w0.x; acc[1] += xv * w0.y;
        acc[2] += xv * w0.z; acc[3] += xv * w0.w;
        acc[4] += xv * w1.x; acc[5] += xv * w1.y;
        acc[6] += xv * w1.z; acc[7] += xv * w1.w;
    }
#pragma unroll
    for (int e = 0; e < N_EXP; e++)
#pragma unroll
        for (int o = 16; o > 0; o >>= 1)
            acc[e] += __shfl_xor_sync(0xffffffffu, acc[e], o);
    if (lane == 0) {
        int e1 = 0; float l1 = acc[0];
#pragma unroll
        for (int e = 1; e < N_EXP; e++)
            if (acc[e] > l1) { l1 = acc[e]; e1 = e; }
        int e2 = (e1 == 0) ? 1 : 0; float l2 = acc[e2];
#pragma unroll
        for (int e = 0; e < N_EXP; e++)
            if (e != e1 && acc[e] > l2) { l2 = acc[e]; e2 = e; }
        float g1 = 1.f / (1.f + expf(l2 - l1));
        float g2 = 1.f - g1;
        int p1 = atomicAdd(&g_count[e1], 1);
        g_rows[e1 * T_TOK + p1] = tok; g_gate[e1 * T_TOK + p1] = g1;
        int p2 = atomicAdd(&g_count[e2], 1);
        g_rows[e2 * T_TOK + p2] = tok; g_gate[e2 * T_TOK + p2] = g2;
    }
}

__global__ void offsets_kernel() {
    if (threadIdx.x != 0) return;
    int s = 0, t = 0;
    for (int e = 0; e < N_EXP; e++) {
        g_off[e] = s;
        int ct = (g_count[e] + 127) >> 7;
        for (int m = 0; m < ct; m++) { g_tileE[t] = e; g_tileM[t] = m << 7; t++; }
        s += ct << 7;
    }
    g_off[N_EXP] = s;
    g_ntiles = t;
}

// gather + per-row two-digit int8 quantization of x (digits: q1 + q2/254)
__global__ void quant_x(const float* __restrict__ x) {
    int r = blockIdx.x;
    int e = 0;
#pragma unroll
    for (int k = 1; k < N_EXP; k++) if (r >= g_off[k]) e = k;
    int i = r - g_off[e];
    int tok = (i < g_count[e] && r < g_off[N_EXP]) ? g_rows[e * T_TOK + i] : -1;
    int tid = threadIdx.x;
    if (tid == 0) {
        g_stok[r]  = tok;
        g_sgate[r] = (tok >= 0) ? g_gate[e * T_TOK + i] : 0.f;
    }
    __shared__ float wmax[8];
    float v[4] = {0.f, 0.f, 0.f, 0.f};
    if (tok >= 0) {
        float4 t = ((const float4*)(x + (size_t)tok * D_MODEL))[tid];
        v[0] = t.x; v[1] = t.y; v[2] = t.z; v[3] = t.w;
    }
    float m = fmaxf(fmaxf(fabsf(v[0]), fabsf(v[1])), fmaxf(fabsf(v[2]), fabsf(v[3])));
#pragma unroll
    for (int o = 16; o; o >>= 1) m = fmaxf(m, __shfl_xor_sync(~0u, m, o));
    if ((tid & 31) == 0) wmax[tid >> 5] = m;
    __syncthreads();
    float M = wmax[0];
#pragma unroll
    for (int j = 1; j < 8; j++) M = fmaxf(M, wmax[j]);
    float s    = (M > 0.f) ? M / 127.f : 1.f;
    float inv  = (M > 0.f) ? 127.f / M : 0.f;
    float inv2 = inv * RDIG;                 // res -> digit2 units
    if (tid == 0) g_sx[r] = s;
    int8_t q1[4], q2[4];
#pragma unroll
    for (int j = 0; j < 4; j++) {
        float q = rintf(v[j] * inv);
        q1[j] = (int8_t)q;
        q2[j] = clamp8(rintf((v[j] - q * s) * inv2));
    }
    size_t off = (size_t)r * D_MODEL + tid * 4;
    *(char4*)(g_X1 + off) = *(char4*)q1;
    *(char4*)(g_X2 + off) = *(char4*)q2;
}

// per-(e,n) colmax of |W|  (W is [E][K][N])
__global__ void colmax_w(const float* __restrict__ W, unsigned* cm, int K, int N) {
    int e = blockIdx.z;
    int col = blockIdx.x * 256 + threadIdx.x;
    int k0 = blockIdx.y * 128;
    const float* p = W + ((size_t)e * K + k0) * N + col;
    float m = 0.f;
#pragma unroll 4
    for (int k = 0; k < 128; k++) m = fmaxf(m, fabsf(p[(size_t)k * N]));
    atomicMax(cm + (size_t)e * N + col, __float_as_uint(m));
}

// transpose + two-digit quantize: W[e][K][N] fp32 -> D1/D2[e][N][K] int8
__global__ void transquant_w(const float* __restrict__ W,
                             int8_t* __restrict__ D1, int8_t* __restrict__ D2,
                             const unsigned* __restrict__ cm, int K, int N) {
    __shared__ float t[32][33];
    int e  = blockIdx.z;
    int k0 = blockIdx.y * 32, n0 = blockIdx.x * 32;
    const float* Wp = W + ((size_t)e * K + k0) * N + n0;
    for (int i = threadIdx.y; i < 32; i += 8)
        t[i][threadIdx.x] = Wp[(size_t)i * N + threadIdx.x];
    __syncthreads();
    size_t base = ((size_t)e * N + n0) * K + k0;
    for (int i = threadIdx.y; i < 32; i += 8) {
        float cmax = __uint_as_float(cm[(size_t)e * N + n0 + i]);
        float s    = cmax / 127.f;
        float inv  = (cmax > 0.f) ? 127.f / cmax : 0.f;
        float w = t[threadIdx.x][i];
        float q = rintf(w * inv);
        D1[base + (size_t)i * K + threadIdx.x] = (int8_t)q;
        D2[base + (size_t)i * K + threadIdx.x] = clamp8(rintf((w - q * s) * inv * RDIG));
    }
}

// ---------------------------------------------------------------------------
// IMMA GEMM: 128x128 tile, BK=128 int8, 3-stage cp.async pipeline.
// Terms: q1q1 (scale sa*sb), cross (q1a q2b + q2a q1b, scale sa*sb/254); q2q2 dropped.
// Stage (64KB): A1 16K | A2 16K | B1 16K | B2 16K
static constexpr int STG_BYTES = 65536;
static constexpr int SMEM_GEMM = 3 * STG_BYTES;

#define LOAD_STAGE(s, ktile) do {                                              \
    uint32_t st_ = sb + (uint32_t)(s) * STG_BYTES;                             \
    int k0_ = (ktile) * 128;                                                   \
    _Pragma("unroll")                                                          \
    for (int i_ = 0; i_ < 4; i_++) {                                           \
        int idx_ = tid + i_ * 256;                                             \
        int r_  = idx_ >> 3;                                                   \
        int cb_ = (idx_ & 7) << 4;                                             \
        uint32_t sw_ = SWZ(r_ * 128 + cb_);                                    \
        size_t ga_ = (size_t)(rowA0 + r_) * KTOT + k0_ + cb_;                  \
        size_t gb_ = (size_t)(bRow0 + r_) * KTOT + k0_ + cb_;                  \
        cp16(st_ + sw_,         A1 + ga_);                                     \
        cp16(st_ + 16384 + sw_, A2 + ga_);                                     \
        cp16(st_ + 32768 + sw_, B1 + gb_);                                     \
        cp16(st_ + 49152 + sw_, B2 + gb_);                                     \
    }                                                                          \
    asm volatile("cp.async.commit_group;" ::: "memory");                       \
} while (0)

template<int PASS>
__global__ void __launch_bounds__(256, 1)
gemm_imma(const int8_t* __restrict__ A1, const int8_t* __restrict__ A2,
          const int8_t* __restrict__ B1, const int8_t* __restrict__ B2,
          const unsigned* __restrict__ cmB,
          const float* __restrict__ bias, float* __restrict__ out)
{
    constexpr int KTOT = (PASS == 0) ? D_MODEL : D_FF;
    constexpr int NTOT = (PASS == 0) ? D_FF : D_MODEL;
    constexpr int KIT  = KTOT / 128;

    int t = blockIdx.y;
    if (t >= g_ntiles) return;
    int e     = g_tileE[t];
    int rowA0 = g_off[e] + g_tileM[t];
    int n0    = blockIdx.x * 128;
    int bRow0 = e * NTOT + n0;

    extern __shared__ char smem[];
    uint32_t sb = smem_u32(smem);

    int tid = threadIdx.x;
    int wid = tid >> 5, lane = tid & 31;
    int wm = wid >> 2, wn = wid & 3;       // warp tile 64x32

    int acc11[4][4][4], accx[4][4][4];
#pragma unroll
    for (int a = 0; a < 4; a++)
#pragma unroll
        for (int b = 0; b < 4; b++)
#pragma unroll
            for (int c = 0; c < 4; c++) { acc11[a][b][c] = 0; accx[a][b][c] = 0; }

    LOAD_STAGE(0, 0);
    LOAD_STAGE(1, 1);

    for (int kt = 0; kt < KIT; kt++) {
        asm volatile("cp.async.wait_group 1;" ::: "memory");
        __syncthreads();
        int s = kt % 3;
        uint32_t sA = sb + (uint32_t)s * STG_BYTES;
        uint32_t sB = sA + 32768;
#pragma unroll
        for (int k32 = 0; k32 < 4; k32++) {
            uint32_t a_1[4][4], a_2[4][4], b_1[2][4], b_2[2][4];
#pragma unroll
            for (int mt = 0; mt < 4; mt++) {
                uint32_t ad = sA + SWZ((wm * 64 + mt * 16 + (lane & 15)) * 128
                                       + k32 * 32 + (lane >> 4) * 16);
                ldsm4(a_1[mt], ad);
                ldsm4(a_2[mt], ad + 16384);
            }
#pragma unroll
            for (int nt = 0; nt < 2; nt++) {
                uint32_t bd = sB + SWZ((wn * 32 + nt * 16 + (lane & 15)) * 128
                                       + k32 * 32 + (lane >> 4) * 16);
                ldsm4(b_1[nt], bd);
                ldsm4(b_2[nt], bd + 16384);
            }
#pragma unroll
            for (int mt = 0; mt < 4; mt++)
#pragma unroll
                for (int n8 = 0; n8 < 4; n8++) {
                    int nt = n8 >> 1, hf = n8 & 1;
                    uint32_t p1[2] = { b_1[nt][hf], b_1[nt][2 + hf] };
                    uint32_t p2[2] = { b_2[nt][hf], b_2[nt][2 + hf] };
                    mma_s8(acc11[mt][n8], a_1[mt], p1);
                    mma_s8(accx [mt][n8], a_1[mt], p2);
                    mma_s8(accx [mt][n8], a_2[mt], p1);
                }
        }
        if (kt + 2 < KIT) { LOAD_STAGE((kt + 2) % 3, kt + 2); }
        else asm volatile("cp.async.commit_group;" ::: "memory");
    }
    asm volatile("cp.async.wait_group 0;" ::: "memory");
    __syncthreads();

    // ---- epilogue ----
    const float* bp = bias + (size_t)e * NTOT;
    const unsigned* cb = cmB + (size_t)e * NTOT + n0;
    int8_t* sm1 = (int8_t*)smem;
    int8_t* sm2 = (int8_t*)smem + 16384;
#pragma unroll
    for (int mt = 0; mt < 4; mt++) {
        int r0 = wm * 64 + mt * 16 + (lane >> 2);
        float sa0, sa1;
        if (PASS == 0) { sa0 = g_sx[rowA0 + r0]; sa1 = g_sx[rowA0 + r0 + 8]; }
        else           { sa0 = S_H;              sa1 = S_H; }
#pragma unroll
        for (int n8 = 0; n8 < 4; n8++) {
            int c0 = wn * 32 + n8 * 8 + (lane & 3) * 2;
            float sb0 = __uint_as_float(cb[c0])     * (1.f / 127.f);
            float sb1 = __uint_as_float(cb[c0 + 1]) * (1.f / 127.f);
            int* i11 = acc11[mt][n8];
            int* ix  = accx [mt][n8];
            float v0 = sa0 * sb0 * ((float)i11[0] + (float)ix[0] * (1.f / RDIG));
            float v1 = sa0 * sb1 * ((float)i11[1] + (float)ix[1] * (1.f / RDIG));
            float v2 = sa1 * sb0 * ((float)i11[2] + (float)ix[2] * (1.f / RDIG));
            float v3 = sa1 * sb1 * ((float)i11[3] + (float)ix[3] * (1.f / RDIG));
            float bb0 = bp[n0 + c0], bb1 = bp[n0 + c0 + 1];
            if (PASS == 0) {
                float h0 = fmaxf(v0 + bb0, 0.f), h1 = fmaxf(v1 + bb1, 0.f);
                float h2 = fmaxf(v2 + bb0, 0.f), h3 = fmaxf(v3 + bb1, 0.f);
                float q0 = fminf(rintf(h0 * INV_S_H), 127.f);
                float q1 = fminf(rintf(h1 * INV_S_H), 127.f);
                float q2 = fminf(rintf(h2 * INV_S_H), 127.f);
                float q3 = fminf(rintf(h3 * INV_S_H), 127.f);
                sm1[r0 * 128 + c0]           = (int8_t)q0;
                sm1[r0 * 128 + c0 + 1]       = (int8_t)q1;
                sm1[(r0 + 8) * 128 + c0]     = (int8_t)q2;
                sm1[(r0 + 8) * 128 + c0 + 1] = (int8_t)q3;
                sm2[r0 * 128 + c0]           = clamp8(rintf((h0 - q0 * S_H) * INV_S_H * RDIG));
                sm2[r0 * 128 + c0 + 1]       = clamp8(rintf((h1 - q1 * S_H) * INV_S_H * RDIG));
                sm2[(r0 + 8) * 128 + c0]     = clamp8(rintf((h2 - q2 * S_H) * INV_S_H * RDIG));
                sm2[(r0 + 8) * 128 + c0 + 1] = clamp8(rintf((h3 - q3 * S_H) * INV_S_H * RDIG));
            } else {
                int row = rowA0 + r0;
                int tok0 = g_stok[row], tok1 = g_stok[row + 8];
                if (tok0 >= 0) {
                    float g = g_sgate[row];
                    atomicAdd(out + (size_t)tok0 * D_MODEL + n0 + c0,     g * (v0 + bb0));
                    atomicAdd(out + (size_t)tok0 * D_MODEL + n0 + c0 + 1, g * (v1 + bb1));
                }
                if (tok1 >= 0) {
                    float g = g_sgate[row + 8];
                    atomicAdd(out + (size_t)tok1 * D_MODEL + n0 + c0,     g * (v2 + bb0));
                    atomicAdd(out + (size_t)tok1 * D_MODEL + n0 + c0 + 1, g * (v3 + bb1));
                }
            }
        }
    }
    if (PASS == 0) {
        __syncthreads();
#pragma unroll
        for (int i = 0; i < 4; i++) {
            int idx = tid + i * 256;
            int r = idx >> 3, cbp = (idx & 7) << 4;
            int4 v1 = *(int4*)(sm1 + r * 128 + cbp);
            int4 v2 = *(int4*)(sm2 + r * 128 + cbp);
            *(int4*)(g_H1 + (size_t)(rowA0 + r) * D_FF + n0 + cbp) = v1;
            *(int4*)(g_H2 + (size_t)(rowA0 + r) * D_FF + n0 + cbp) = v2;
        }
    }
}

// ---------------------------------------------------------------------------
extern "C" void kernel_launch(void* const* d_in, const int* in_sizes, int n_in,
                              void* d_out, int out_size) {
    const float* x  = (const float*)d_in[0];
    const float* Wr = (const float*)d_in[1];
    const float* W1 = (const float*)d_in[2];
    const float* b1 = (const float*)d_in[3];
    const float* W2 = (const float*)d_in[4];
    const float* b2 = (const float*)d_in[5];
    float* out = (float*)d_out;

    void *pX1, *pX2, *pW11, *pW12, *pW21, *pW22, *pH1, *pH2, *pCM1, *pCM2;
    cudaGetSymbolAddress(&pX1,  g_X1);   cudaGetSymbolAddress(&pX2,  g_X2);
    cudaGetSymbolAddress(&pW11, g_W1T1); cudaGetSymbolAddress(&pW12, g_W1T2);
    cudaGetSymbolAddress(&pW21, g_W2T1); cudaGetSymbolAddress(&pW22, g_W2T2);
    cudaGetSymbolAddress(&pH1,  g_H1);   cudaGetSymbolAddress(&pH2,  g_H2);
    cudaGetSymbolAddress(&pCM1, g_cm1);  cudaGetSymbolAddress(&pCM2, g_cm2);

    cudaFuncSetAttribute(gemm_imma<0>, cudaFuncAttributeMaxDynamicSharedMemorySize, SMEM_GEMM);
    cudaFuncSetAttribute(gemm_imma<1>, cudaFuncAttributeMaxDynamicSharedMemorySize, SMEM_GEMM);

    cudaMemsetAsync(out, 0, (size_t)out_size * sizeof(float));
    cudaMemsetAsync(pCM1, 0, N_EXP * D_FF * sizeof(unsigned));
    cudaMemsetAsync(pCM2, 0, N_EXP * D_MODEL * sizeof(unsigned));
    zero_counts_kernel<<<1, 32>>>();
    router_kernel<<<T_TOK / 8, 256>>>(x, Wr);
    offsets_kernel<<<1, 1>>>();
    quant_x<<<XG_ROWS, 256>>>(x);

    colmax_w<<<dim3(D_FF / 256, D_MODEL / 128, N_EXP), 256>>>(W1, (unsigned*)pCM1, D_MODEL, D_FF);
    colmax_w<<<dim3(D_MODEL / 256, D_FF / 128, N_EXP), 256>>>(W2, (unsigned*)pCM2, D_FF, D_MODEL);

    dim3 tb(32, 8);
    transquant_w<<<dim3(D_FF / 32, D_MODEL / 32, N_EXP), tb>>>(
        W1, (int8_t*)pW11, (int8_t*)pW12, (const unsigned*)pCM1, D_MODEL, D_FF);
    transquant_w<<<dim3(D_MODEL / 32, D_FF / 32, N_EXP), tb>>>(
        W2, (int8_t*)pW21, (int8_t*)pW22, (const unsigned*)pCM2, D_FF, D_MODEL);

    gemm_imma<0><<<dim3(D_FF / 128, MAX_TILES), 256, SMEM_GEMM>>>(
        (const int8_t*)pX1, (const int8_t*)pX2, (const int8_t*)pW11, (const int8_t*)pW12,
        (const unsigned*)pCM1, b1, out);
    gemm_imma<1><<<dim3(D_MODEL / 128, MAX_TILES), 256, SMEM_GEMM>>>(
        (const int8_t*)pH1, (const int8_t*)pH2, (const int8_t*)pW21, (const int8_t*)pW22,
        (const unsigned*)pCM2, b2, out);
}

// round 6
// speedup vs baseline: 2.5013x; 2.5013x over previous
#include <cuda_runtime.h>
#include <cuda_bf16.h>
#include <math.h>
#include <stdint.h>

#define D_MODEL 1024
#define D_FF    4096
#define N_EXP   8
#define T_TOK   4096
#define XG_ROWS 9216          // 8192 + 8*128 padding
#define MAX_TILES 72

// ---- scratch (__device__ globals; no cudaMalloc allowed) --------------------
__device__ int   g_count[N_EXP];
__device__ int   g_off[N_EXP + 1];
__device__ int   g_rows[N_EXP * T_TOK];
__device__ float g_gate[N_EXP * T_TOK];
__device__ int   g_tileE[MAX_TILES];
__device__ int   g_tileM[MAX_TILES];
__device__ int   g_ntiles;
__device__ int   g_stok[XG_ROWS];
__device__ float g_sgate[XG_ROWS];

__device__ __nv_bfloat16 g_Xg_hi[(size_t)XG_ROWS * D_MODEL];
__device__ __nv_bfloat16 g_Xg_lo[(size_t)XG_ROWS * D_MODEL];
__device__ __nv_bfloat16 g_W1T_hi[(size_t)N_EXP * D_FF * D_MODEL];
__device__ __nv_bfloat16 g_W1T_lo[(size_t)N_EXP * D_FF * D_MODEL];
__device__ __nv_bfloat16 g_W2T_hi[(size_t)N_EXP * D_MODEL * D_FF];
__device__ __nv_bfloat16 g_W2T_lo[(size_t)N_EXP * D_MODEL * D_FF];
__device__ __nv_bfloat16 g_H_hi[(size_t)XG_ROWS * D_FF];
__device__ __nv_bfloat16 g_H_lo[(size_t)XG_ROWS * D_FF];

// ---- helpers ----------------------------------------------------------------
#define SWZ(o) ((o) ^ (((o) >> 3) & 0x70))

__device__ __forceinline__ uint32_t smem_u32(const void* p) {
    uint32_t a;
    asm("{ .reg .u64 t; cvta.to.shared.u64 t, %1; cvt.u32.u64 %0, t; }"
        : "=r"(a) : "l"(p));
    return a;
}
__device__ __forceinline__ void cp16(uint32_t dst, const void* src) {
    asm volatile("cp.async.cg.shared.global [%0], [%1], 16;"
                 :: "r"(dst), "l"(src) : "memory");
}
__device__ __forceinline__ void ldsm4(uint32_t* r, uint32_t addr) {
    asm volatile("ldmatrix.sync.aligned.m8n8.x4.shared.b16 {%0,%1,%2,%3}, [%4];"
                 : "=r"(r[0]), "=r"(r[1]), "=r"(r[2]), "=r"(r[3]) : "r"(addr));
}
__device__ __forceinline__ void mma_bf16(float* d, const uint32_t* a, const uint32_t* b) {
    asm volatile("mma.sync.aligned.m16n8k16.row.col.f32.bf16.bf16.f32 "
        "{%0,%1,%2,%3}, {%4,%5,%6,%7}, {%8,%9}, {%0,%1,%2,%3};"
        : "+f"(d[0]), "+f"(d[1]), "+f"(d[2]), "+f"(d[3])
        : "r"(a[0]), "r"(a[1]), "r"(a[2]), "r"(a[3]), "r"(b[0]), "r"(b[1]));
}
__device__ __forceinline__ void split2(float v, __nv_bfloat16& h, __nv_bfloat16& l) {
    h = __float2bfloat16(v);
    l = __float2bfloat16(v - __bfloat162float(h));
}

// ---- routing ----------------------------------------------------------------
__global__ void zero_counts_kernel() {
    if (threadIdx.x < N_EXP) g_count[threadIdx.x] = 0;
}

__global__ void router_kernel(const float* __restrict__ x,
                              const float* __restrict__ Wr) {
    int tok  = (blockIdx.x * blockDim.x + threadIdx.x) >> 5;
    int lane = threadIdx.x & 31;
    if (tok >= T_TOK) return;
    const float* xr = x + (size_t)tok * D_MODEL;
    float acc[N_EXP];
#pragma unroll
    for (int e = 0; e < N_EXP; e++) acc[e] = 0.f;
    for (int d = lane; d < D_MODEL; d += 32) {
        float xv = xr[d];
        float4 w0 = *(const float4*)(Wr + (size_t)d * N_EXP);
        float4 w1 = *(const float4*)(Wr + (size_t)d * N_EXP + 4);
        acc[0] += xv * w0.x; acc[1] += xv * w0.y;
        acc[2] += xv * w0.z; acc[3] += xv * w0.w;
        acc[4] += xv * w1.x; acc[5] += xv * w1.y;
        acc[6] += xv * w1.z; acc[7] += xv * w1.w;
    }
#pragma unroll
    for (int e = 0; e < N_EXP; e++)
#pragma unroll
        for (int o = 16; o > 0; o >>= 1)
            acc[e] += __shfl_xor_sync(0xffffffffu, acc[e], o);
    if (lane == 0) {
        int e1 = 0; float l1 = acc[0];
#pragma unroll
        for (int e = 1; e < N_EXP; e++)
            if (acc[e] > l1) { l1 = acc[e]; e1 = e; }
        int e2 = (e1 == 0) ? 1 : 0; float l2 = acc[e2];
#pragma unroll
        for (int e = 0; e < N_EXP; e++)
            if (e != e1 && acc[e] > l2) { l2 = acc[e]; e2 = e; }
        float g1 = 1.f / (1.f + expf(l2 - l1));
        float g2 = 1.f - g1;
        int p1 = atomicAdd(&g_count[e1], 1);
        g_rows[e1 * T_TOK + p1] = tok; g_gate[e1 * T_TOK + p1] = g1;
        int p2 = atomicAdd(&g_count[e2], 1);
        g_rows[e2 * T_TOK + p2] = tok; g_gate[e2 * T_TOK + p2] = g2;
    }
}

__global__ void offsets_kernel() {
    if (threadIdx.x != 0) return;
    int s = 0, t = 0;
    for (int e = 0; e < N_EXP; e++) {
        g_off[e] = s;
        int ct = (g_count[e] + 127) >> 7;
        for (int m = 0; m < ct; m++) { g_tileE[t] = e; g_tileM[t] = m << 7; t++; }
        s += ct << 7;
    }
    g_off[N_EXP] = s;
    g_ntiles = t;
}

// gather tokens to padded layout; split fp32 -> bf16 hi/lo; zero pad rows
__global__ void gather_split_x(const float* __restrict__ x) {
    int r = blockIdx.x;
    if (r >= g_off[N_EXP]) return;
    int e = 0;
#pragma unroll
    for (int k = 1; k < N_EXP; k++) if (r >= g_off[k]) e = k;
    int i = r - g_off[e];
    int tok = (i < g_count[e]) ? g_rows[e * T_TOK + i] : -1;
    if (threadIdx.x == 0) {
        g_stok[r]  = tok;
        g_sgate[r] = (tok >= 0) ? g_gate[e * T_TOK + i] : 0.f;
    }
    size_t base = (size_t)r * D_MODEL;
    if (tok < 0) {
        __nv_bfloat162 z; z.x = __float2bfloat16(0.f); z.y = z.x;
        for (int c = threadIdx.x; c < D_MODEL / 2; c += blockDim.x) {
            *(__nv_bfloat162*)(g_Xg_hi + base + 2 * c) = z;
            *(__nv_bfloat162*)(g_Xg_lo + base + 2 * c) = z;
        }
        return;
    }
    const float2* xp = (const float2*)(x + (size_t)tok * D_MODEL);
    for (int c = threadIdx.x; c < D_MODEL / 2; c += blockDim.x) {
        float2 v = xp[c];
        __nv_bfloat162 h, l;
        split2(v.x, h.x, l.x);
        split2(v.y, h.y, l.y);
        *(__nv_bfloat162*)(g_Xg_hi + base + 2 * c) = h;
        *(__nv_bfloat162*)(g_Xg_lo + base + 2 * c) = l;
    }
}

// transpose + split, vectorized stores: W[e][K][N] fp32 -> WT_hi/lo[e][N][K] bf16
// tile: 64 K x 32 N, block (32,8)
__global__ void transpose_split(const float* __restrict__ W,
                                __nv_bfloat16* __restrict__ hi,
                                __nv_bfloat16* __restrict__ lo,
                                int K, int N) {
    __shared__ float t[64][33];
    int e  = blockIdx.z;
    int k0 = blockIdx.y * 64, n0 = blockIdx.x * 32;
    int tx = threadIdx.x, ty = threadIdx.y;
    const float* Wp = W + ((size_t)e * K + k0) * N + n0;
#pragma unroll
    for (int i = ty; i < 64; i += 8)
        t[i][tx] = Wp[(size_t)i * N + tx];
    __syncthreads();
    size_t base = ((size_t)e * N + n0) * K + k0;
#pragma unroll
    for (int j = ty; j < 32; j += 8) {
        float v0 = t[2 * tx][j], v1 = t[2 * tx + 1][j];
        __nv_bfloat162 h, l;
        split2(v0, h.x, l.x);
        split2(v1, h.y, l.y);
        *(__nv_bfloat162*)(hi + base + (size_t)j * K + 2 * tx) = h;
        *(__nv_bfloat162*)(lo + base + (size_t)j * K + 2 * tx) = l;
    }
}

// ---------------------------------------------------------------------------
// mma.sync GEMM: 128x256 CTA tile, 512 threads, BK=64, 2-stage cp.async.
// D = Ahi*Bhi + Ahi*Blo + Alo*Bhi (fp32 acc).
// Stage layout (96 KB): A_hi 16K | A_lo 16K | B_hi 32K | B_lo 32K
static constexpr int STG_BYTES = 98304;
static constexpr int SMEM_GEMM = 2 * STG_BYTES;

#define LOAD_STAGE(s, ktile) do {                                              \
    uint32_t st_ = sb + (uint32_t)(s) * STG_BYTES;                             \
    int k0_ = (ktile) * 64;                                                    \
    int rb_ = tid >> 3;                                                        \
    int cb_ = (tid & 7) << 4;                                                  \
    _Pragma("unroll")                                                          \
    for (int i_ = 0; i_ < 2; i_++) {                                           \
        int r_ = rb_ + i_ * 64;                                                \
        uint32_t sw_ = SWZ(r_ * 128 + cb_);                                    \
        size_t ga_ = ((size_t)(rowA0 + r_) * KTOT + k0_) * 2 + cb_;            \
        cp16(st_ + sw_,         (const char*)Ah + ga_);                        \
        cp16(st_ + 16384 + sw_, (const char*)Al + ga_);                        \
    }                                                                          \
    _Pragma("unroll")                                                          \
    for (int i_ = 0; i_ < 4; i_++) {                                           \
        int r_ = rb_ + i_ * 64;                                                \
        uint32_t sw_ = SWZ(r_ * 128 + cb_);                                    \
        size_t gb_ = ((size_t)(bRow0 + r_) * KTOT + k0_) * 2 + cb_;            \
        cp16(st_ + 32768 + sw_, (const char*)Bh + gb_);                        \
        cp16(st_ + 65536 + sw_, (const char*)Bl + gb_);                        \
    }                                                                          \
    asm volatile("cp.async.commit_group;" ::: "memory");                       \
} while (0)

template<int PASS>
__global__ void __launch_bounds__(512, 1)
gemm_mma(const __nv_bfloat16* __restrict__ Ah, const __nv_bfloat16* __restrict__ Al,
         const __nv_bfloat16* __restrict__ Bh, const __nv_bfloat16* __restrict__ Bl,
         const float* __restrict__ bias, float* __restrict__ out)
{
    constexpr int KTOT = (PASS == 0) ? D_MODEL : D_FF;
    constexpr int NTOT = (PASS == 0) ? D_FF : D_MODEL;
    constexpr int KIT  = KTOT / 64;

    int t = blockIdx.y;
    if (t >= g_ntiles) return;
    int e     = g_tileE[t];
    int rowA0 = g_off[e] + g_tileM[t];
    int n0    = blockIdx.x * 256;
    int bRow0 = e * NTOT + n0;

    extern __shared__ char smem[];
    uint32_t sb = smem_u32(smem);

    int tid = threadIdx.x;
    int wid = tid >> 5, lane = tid & 31;
    int wm = wid >> 3, wn = wid & 7;       // warp tile: rows wm*64, cols wn*32

    float acc[4][4][4];
#pragma unroll
    for (int a = 0; a < 4; a++)
#pragma unroll
        for (int b = 0; b < 4; b++)
#pragma unroll
            for (int c = 0; c < 4; c++) acc[a][b][c] = 0.f;

    LOAD_STAGE(0, 0);
    LOAD_STAGE(1, 1);

    for (int kt = 0; kt < KIT; kt++) {
        if (kt + 1 < KIT) asm volatile("cp.async.wait_group 1;" ::: "memory");
        else              asm volatile("cp.async.wait_group 0;" ::: "memory");
        __syncthreads();
        uint32_t sA = sb + (uint32_t)(kt & 1) * STG_BYTES;
        uint32_t sB = sA + 32768;
#pragma unroll
        for (int k16 = 0; k16 < 4; k16++) {
            uint32_t b_h[2][4], b_l[2][4];
#pragma unroll
            for (int nt = 0; nt < 2; nt++) {
                uint32_t bd = sB + SWZ((wn * 32 + nt * 16 + (lane & 15)) * 128
                                       + k16 * 32 + (lane >> 4) * 16);
                ldsm4(b_h[nt], bd);
                ldsm4(b_l[nt], bd + 32768);
            }
#pragma unroll
            for (int mt = 0; mt < 4; mt++) {
                uint32_t a_h[4], a_l[4];
                uint32_t ad = sA + SWZ((wm * 64 + mt * 16 + (lane & 15)) * 128
                                       + k16 * 32 + (lane >> 4) * 16);
                ldsm4(a_h, ad);
                ldsm4(a_l, ad + 16384);
#pragma unroll
                for (int n8 = 0; n8 < 4; n8++) {
                    int nt = n8 >> 1, hf = n8 & 1;
                    uint32_t bh[2] = { b_h[nt][hf], b_h[nt][2 + hf] };
                    uint32_t bl[2] = { b_l[nt][hf], b_l[nt][2 + hf] };
                    mma_bf16(acc[mt][n8], a_h, bh);
                    mma_bf16(acc[mt][n8], a_h, bl);
                    mma_bf16(acc[mt][n8], a_l, bh);
                }
            }
        }
        __syncthreads();
        if (kt + 2 < KIT) { LOAD_STAGE(kt & 1, kt + 2); }
    }

    // ---- epilogue ----
    const float* bp = bias + (size_t)e * NTOT;
#pragma unroll
    for (int mt = 0; mt < 4; mt++) {
        int r0 = wm * 64 + mt * 16 + (lane >> 2);
#pragma unroll
        for (int n8 = 0; n8 < 4; n8++) {
            int cg = n0 + wn * 32 + n8 * 8 + (lane & 3) * 2;
            float* a = acc[mt][n8];
            float bb0 = bp[cg], bb1 = bp[cg + 1];
            int row = rowA0 + r0;
            if (PASS == 0) {
                float v0 = fmaxf(a[0] + bb0, 0.f), v1 = fmaxf(a[1] + bb1, 0.f);
                float v2 = fmaxf(a[2] + bb0, 0.f), v3 = fmaxf(a[3] + bb1, 0.f);
                __nv_bfloat162 h, l;
                split2(v0, h.x, l.x); split2(v1, h.y, l.y);
                *(__nv_bfloat162*)(g_H_hi + (size_t)row * D_FF + cg) = h;
                *(__nv_bfloat162*)(g_H_lo + (size_t)row * D_FF + cg) = l;
                split2(v2, h.x, l.x); split2(v3, h.y, l.y);
                *(__nv_bfloat162*)(g_H_hi + (size_t)(row + 8) * D_FF + cg) = h;
                *(__nv_bfloat162*)(g_H_lo + (size_t)(row + 8) * D_FF + cg) = l;
            } else {
                int tok0 = g_stok[row], tok1 = g_stok[row + 8];
                if (tok0 >= 0) {
                    float g = g_sgate[row];
                    atomicAdd(out + (size_t)tok0 * D_MODEL + cg,     g * (a[0] + bb0));
                    atomicAdd(out + (size_t)tok0 * D_MODEL + cg + 1, g * (a[1] + bb1));
                }
                if (tok1 >= 0) {
                    float g = g_sgate[row + 8];
                    atomicAdd(out + (size_t)tok1 * D_MODEL + cg,     g * (a[2] + bb0));
                    atomicAdd(out + (size_t)tok1 * D_MODEL + cg + 1, g * (a[3] + bb1));
                }
            }
        }
    }
}

// ---------------------------------------------------------------------------
extern "C" void kernel_launch(void* const* d_in, const int* in_sizes, int n_in,
                              void* d_out, int out_size) {
    const float* x  = (const float*)d_in[0];
    const float* Wr = (const float*)d_in[1];
    const float* W1 = (const float*)d_in[2];
    const float* b1 = (const float*)d_in[3];
    const float* W2 = (const float*)d_in[4];
    const float* b2 = (const float*)d_in[5];
    float* out = (float*)d_out;

    void *pXh, *pXl, *pW1h, *pW1l, *pW2h, *pW2l, *pHh, *pHl;
    cudaGetSymbolAddress(&pXh,  g_Xg_hi);  cudaGetSymbolAddress(&pXl,  g_Xg_lo);
    cudaGetSymbolAddress(&pW1h, g_W1T_hi); cudaGetSymbolAddress(&pW1l, g_W1T_lo);
    cudaGetSymbolAddress(&pW2h, g_W2T_hi); cudaGetSymbolAddress(&pW2l, g_W2T_lo);
    cudaGetSymbolAddress(&pHh,  g_H_hi);   cudaGetSymbolAddress(&pHl,  g_H_lo);

    cudaFuncSetAttribute(gemm_mma<0>, cudaFuncAttributeMaxDynamicSharedMemorySize, SMEM_GEMM);
    cudaFuncSetAttribute(gemm_mma<1>, cudaFuncAttributeMaxDynamicSharedMemorySize, SMEM_GEMM);

    cudaMemsetAsync(out, 0, (size_t)out_size * sizeof(float));
    zero_counts_kernel<<<1, 32>>>();
    router_kernel<<<T_TOK / 8, 256>>>(x, Wr);
    offsets_kernel<<<1, 1>>>();

    dim3 tb(32, 8);
    transpose_split<<<dim3(D_FF / 32, D_MODEL / 64, N_EXP), tb>>>(
        W1, (__nv_bfloat16*)pW1h, (__nv_bfloat16*)pW1l, D_MODEL, D_FF);
    transpose_split<<<dim3(D_MODEL / 32, D_FF / 64, N_EXP), tb>>>(
        W2, (__nv_bfloat16*)pW2h, (__nv_bfloat16*)pW2l, D_FF, D_MODEL);
    gather_split_x<<<XG_ROWS, 256>>>(x);

    gemm_mma<0><<<dim3(D_FF / 256, MAX_TILES), 512, SMEM_GEMM>>>(
        (const __nv_bfloat16*)pXh, (const __nv_bfloat16*)pXl,
        (const __nv_bfloat16*)pW1h, (const __nv_bfloat16*)pW1l, b1, out);
    gemm_mma<1><<<dim3(D_MODEL / 256, MAX_TILES), 512, SMEM_GEMM>>>(
        (const __nv_bfloat16*)pHh, (const __nv_bfloat16*)pHl,
        (const __nv_bfloat16*)pW2h, (const __nv_bfloat16*)pW2l, b2, out);
}

// round 7
// speedup vs baseline: 3.4832x; 1.3926x over previous
#include <cuda_runtime.h>
#include <cuda_fp16.h>
#include <math.h>
#include <stdint.h>

#define D_MODEL 1024
#define D_FF    4096
#define N_EXP   8
#define T_TOK   4096
#define XG_ROWS 9216          // 8192 + 8*128 padding
#define MAX_TILES 72

// ---- scratch (__device__ globals; no cudaMalloc allowed) --------------------
__device__ int   g_count[N_EXP];
__device__ int   g_off[N_EXP + 1];
__device__ int   g_rows[N_EXP * T_TOK];
__device__ float g_gate[N_EXP * T_TOK];
__device__ int   g_tileE[MAX_TILES];
__device__ int   g_tileM[MAX_TILES];
__device__ int   g_ntiles;
__device__ int   g_stok[XG_ROWS];
__device__ float g_sgate[XG_ROWS];

__device__ __half g_Xg[(size_t)XG_ROWS * D_MODEL];                 // single digit
__device__ __half g_W1T_hi[(size_t)N_EXP * D_FF * D_MODEL];
__device__ __half g_W1T_lo[(size_t)N_EXP * D_FF * D_MODEL];
__device__ __half g_W2T_hi[(size_t)N_EXP * D_MODEL * D_FF];
__device__ __half g_W2T_lo[(size_t)N_EXP * D_MODEL * D_FF];
__device__ __half g_H[(size_t)XG_ROWS * D_FF];                     // single digit

// ---- helpers ----------------------------------------------------------------
#define SWZ(o) ((o) ^ (((o) >> 3) & 0x70))

__device__ __forceinline__ uint32_t smem_u32(const void* p) {
    uint32_t a;
    asm("{ .reg .u64 t; cvta.to.shared.u64 t, %1; cvt.u32.u64 %0, t; }"
        : "=r"(a) : "l"(p));
    return a;
}
__device__ __forceinline__ void cp16(uint32_t dst, const void* src) {
    asm volatile("cp.async.cg.shared.global [%0], [%1], 16;"
                 :: "r"(dst), "l"(src) : "memory");
}
__device__ __forceinline__ void ldsm4(uint32_t* r, uint32_t addr) {
    asm volatile("ldmatrix.sync.aligned.m8n8.x4.shared.b16 {%0,%1,%2,%3}, [%4];"
                 : "=r"(r[0]), "=r"(r[1]), "=r"(r[2]), "=r"(r[3]) : "r"(addr));
}
__device__ __forceinline__ void mma_f16(float* d, const uint32_t* a, const uint32_t* b) {
    asm volatile("mma.sync.aligned.m16n8k16.row.col.f32.f16.f16.f32 "
        "{%0,%1,%2,%3}, {%4,%5,%6,%7}, {%8,%9}, {%0,%1,%2,%3};"
        : "+f"(d[0]), "+f"(d[1]), "+f"(d[2]), "+f"(d[3])
        : "r"(a[0]), "r"(a[1]), "r"(a[2]), "r"(a[3]), "r"(b[0]), "r"(b[1]));
}
__device__ __forceinline__ void splitw(float v, __half& h, __half& l) {
    h = __float2half_rn(v);
    l = __float2half_rn(v - __half2float(h));
}

// ---- routing ----------------------------------------------------------------
__global__ void zero_counts_kernel() {
    if (threadIdx.x < N_EXP) g_count[threadIdx.x] = 0;
}

__global__ void router_kernel(const float* __restrict__ x,
                              const float* __restrict__ Wr) {
    int tok  = (blockIdx.x * blockDim.x + threadIdx.x) >> 5;
    int lane = threadIdx.x & 31;
    if (tok >= T_TOK) return;
    const float* xr = x + (size_t)tok * D_MODEL;
    float acc[N_EXP];
#pragma unroll
    for (int e = 0; e < N_EXP; e++) acc[e] = 0.f;
    for (int d = lane; d < D_MODEL; d += 32) {
        float xv = xr[d];
        float4 w0 = *(const float4*)(Wr + (size_t)d * N_EXP);
        float4 w1 = *(const float4*)(Wr + (size_t)d * N_EXP + 4);
        acc[0] += xv * w0.x; acc[1] += xv * w0.y;
        acc[2] += xv * w0.z; acc[3] += xv * w0.w;
        acc[4] += xv * w1.x; acc[5] += xv * w1.y;
        acc[6] += xv * w1.z; acc[7] += xv * w1.w;
    }
#pragma unroll
    for (int e = 0; e < N_EXP; e++)
#pragma unroll
        for (int o = 16; o > 0; o >>= 1)
            acc[e] += __shfl_xor_sync(0xffffffffu, acc[e], o);
    if (lane == 0) {
        int e1 = 0; float l1 = acc[0];
#pragma unroll
        for (int e = 1; e < N_EXP; e++)
            if (acc[e] > l1) { l1 = acc[e]; e1 = e; }
        int e2 = (e1 == 0) ? 1 : 0; float l2 = acc[e2];
#pragma unroll
        for (int e = 0; e < N_EXP; e++)
            if (e != e1 && acc[e] > l2) { l2 = acc[e]; e2 = e; }
        float g1 = 1.f / (1.f + expf(l2 - l1));
        float g2 = 1.f - g1;
        int p1 = atomicAdd(&g_count[e1], 1);
        g_rows[e1 * T_TOK + p1] = tok; g_gate[e1 * T_TOK + p1] = g1;
        int p2 = atomicAdd(&g_count[e2], 1);
        g_rows[e2 * T_TOK + p2] = tok; g_gate[e2 * T_TOK + p2] = g2;
    }
}

__global__ void offsets_kernel() {
    if (threadIdx.x != 0) return;
    int s = 0, t = 0;
    for (int e = 0; e < N_EXP; e++) {
        g_off[e] = s;
        int ct = (g_count[e] + 127) >> 7;
        for (int m = 0; m < ct; m++) { g_tileE[t] = e; g_tileM[t] = m << 7; t++; }
        s += ct << 7;
    }
    g_off[N_EXP] = s;
    g_ntiles = t;
}

// gather tokens to padded layout; fp32 -> fp16 single digit; zero pad rows
__global__ void gather_x(const float* __restrict__ x) {
    int r = blockIdx.x;
    if (r >= g_off[N_EXP]) return;
    int e = 0;
#pragma unroll
    for (int k = 1; k < N_EXP; k++) if (r >= g_off[k]) e = k;
    int i = r - g_off[e];
    int tok = (i < g_count[e]) ? g_rows[e * T_TOK + i] : -1;
    if (threadIdx.x == 0) {
        g_stok[r]  = tok;
        g_sgate[r] = (tok >= 0) ? g_gate[e * T_TOK + i] : 0.f;
    }
    size_t base = (size_t)r * D_MODEL;
    if (tok < 0) {
        __half2 z = __floats2half2_rn(0.f, 0.f);
        for (int c = threadIdx.x; c < D_MODEL / 2; c += blockDim.x)
            *(__half2*)(g_Xg + base + 2 * c) = z;
        return;
    }
    const float2* xp = (const float2*)(x + (size_t)tok * D_MODEL);
    for (int c = threadIdx.x; c < D_MODEL / 2; c += blockDim.x) {
        float2 v = xp[c];
        *(__half2*)(g_Xg + base + 2 * c) = __floats2half2_rn(v.x, v.y);
    }
}

// transpose + split: W[e][K][N] fp32 -> WT_hi/lo[e][N][K] fp16
__global__ void transpose_split(const float* __restrict__ W,
                                __half* __restrict__ hi,
                                __half* __restrict__ lo,
                                int K, int N) {
    __shared__ float t[64][33];
    int e  = blockIdx.z;
    int k0 = blockIdx.y * 64, n0 = blockIdx.x * 32;
    int tx = threadIdx.x, ty = threadIdx.y;
    const float* Wp = W + ((size_t)e * K + k0) * N + n0;
#pragma unroll
    for (int i = ty; i < 64; i += 8)
        t[i][tx] = Wp[(size_t)i * N + tx];
    __syncthreads();
    size_t base = ((size_t)e * N + n0) * K + k0;
#pragma unroll
    for (int j = ty; j < 32; j += 8) {
        float v0 = t[2 * tx][j], v1 = t[2 * tx + 1][j];
        __half h0, l0, h1, l1;
        splitw(v0, h0, l0);
        splitw(v1, h1, l1);
        __half2 h; h.x = h0; h.y = h1;
        __half2 l; l.x = l0; l.y = l1;
        *(__half2*)(hi + base + (size_t)j * K + 2 * tx) = h;
        *(__half2*)(lo + base + (size_t)j * K + 2 * tx) = l;
    }
}

// ---------------------------------------------------------------------------
// fp16 mma.sync GEMM: 128x256 CTA tile, 512 threads, BK=64, 2-stage cp.async.
// D = A * (B_hi + B_lo): 2 MMAs per (k16, subtile).  A single fp16 digit.
// Stage (80 KB): A 16K | B_hi 32K | B_lo 32K
static constexpr int STG_BYTES = 81920;
static constexpr int SMEM_GEMM = 2 * STG_BYTES;

#define LOAD_STAGE(s, ktile) do {                                              \
    uint32_t st_ = sb + (uint32_t)(s) * STG_BYTES;                             \
    int k0_ = (ktile) * 64;                                                    \
    _Pragma("unroll")                                                          \
    for (int i_ = 0; i_ < 2; i_++) {                                           \
        int idx_ = tid + i_ * 512;                                             \
        int r_ = idx_ >> 3, cb_ = (idx_ & 7) << 4;                             \
        uint32_t sw_ = SWZ(r_ * 128 + cb_);                                    \
        size_t ga_ = ((size_t)(rowA0 + r_) * KTOT + k0_) * 2 + cb_;            \
        cp16(st_ + sw_, (const char*)Ax + ga_);                                \
    }                                                                          \
    _Pragma("unroll")                                                          \
    for (int i_ = 0; i_ < 4; i_++) {                                           \
        int idx_ = tid + i_ * 512;                                             \
        int r_ = idx_ >> 3, cb_ = (idx_ & 7) << 4;                             \
        uint32_t sw_ = SWZ(r_ * 128 + cb_);                                    \
        size_t gb_ = ((size_t)(bRow0 + r_) * KTOT + k0_) * 2 + cb_;            \
        cp16(st_ + 16384 + sw_, (const char*)Bh + gb_);                        \
        cp16(st_ + 49152 + sw_, (const char*)Bl + gb_);                        \
    }                                                                          \
    asm volatile("cp.async.commit_group;" ::: "memory");                       \
} while (0)

template<int PASS>
__global__ void __launch_bounds__(512, 1)
gemm_mma(const __half* __restrict__ Ax,
         const __half* __restrict__ Bh, const __half* __restrict__ Bl,
         const float* __restrict__ bias, float* __restrict__ out)
{
    constexpr int KTOT = (PASS == 0) ? D_MODEL : D_FF;
    constexpr int NTOT = (PASS == 0) ? D_FF : D_MODEL;
    constexpr int KIT  = KTOT / 64;

    int t = blockIdx.y;
    if (t >= g_ntiles) return;
    int e     = g_tileE[t];
    int rowA0 = g_off[e] + g_tileM[t];
    int n0    = blockIdx.x * 256;
    int bRow0 = e * NTOT + n0;

    extern __shared__ char smem[];
    uint32_t sb = smem_u32(smem);

    int tid = threadIdx.x;
    int wid = tid >> 5, lane = tid & 31;
    int wm = wid >> 3, wn = wid & 7;       // warp tile: rows wm*64, cols wn*32

    float acc[4][4][4];
#pragma unroll
    for (int a = 0; a < 4; a++)
#pragma unroll
        for (int b = 0; b < 4; b++)
#pragma unroll
            for (int c = 0; c < 4; c++) acc[a][b][c] = 0.f;

    LOAD_STAGE(0, 0);
    LOAD_STAGE(1, 1);

    for (int kt = 0; kt < KIT; kt++) {
        if (kt + 1 < KIT) asm volatile("cp.async.wait_group 1;" ::: "memory");
        else              asm volatile("cp.async.wait_group 0;" ::: "memory");
        __syncthreads();
        uint32_t sA = sb + (uint32_t)(kt & 1) * STG_BYTES;
        uint32_t sB = sA + 16384;
#pragma unroll
        for (int k16 = 0; k16 < 4; k16++) {
            uint32_t b_h[2][4], b_l[2][4];
#pragma unroll
            for (int nt = 0; nt < 2; nt++) {
                uint32_t bd = sB + SWZ((wn * 32 + nt * 16 + (lane & 15)) * 128
                                       + k16 * 32 + (lane >> 4) * 16);
                ldsm4(b_h[nt], bd);
                ldsm4(b_l[nt], bd + 32768);
            }
#pragma unroll
            for (int mt = 0; mt < 4; mt++) {
                uint32_t a_f[4];
                uint32_t ad = sA + SWZ((wm * 64 + mt * 16 + (lane & 15)) * 128
                                       + k16 * 32 + (lane >> 4) * 16);
                ldsm4(a_f, ad);
#pragma unroll
                for (int n8 = 0; n8 < 4; n8++) {
                    int nt = n8 >> 1, hf = n8 & 1;
                    uint32_t bh[2] = { b_h[nt][hf], b_h[nt][2 + hf] };
                    uint32_t bl[2] = { b_l[nt][hf], b_l[nt][2 + hf] };
                    mma_f16(acc[mt][n8], a_f, bh);
                    mma_f16(acc[mt][n8], a_f, bl);
                }
            }
        }
        __syncthreads();
        if (kt + 2 < KIT) { LOAD_STAGE(kt & 1, kt + 2); }
    }

    // ---- epilogue ----
    const float* bp = bias + (size_t)e * NTOT;
#pragma unroll
    for (int mt = 0; mt < 4; mt++) {
        int r0 = wm * 64 + mt * 16 + (lane >> 2);
#pragma unroll
        for (int n8 = 0; n8 < 4; n8++) {
            int cg = n0 + wn * 32 + n8 * 8 + (lane & 3) * 2;
            float* a = acc[mt][n8];
            float bb0 = bp[cg], bb1 = bp[cg + 1];
            int row = rowA0 + r0;
            if (PASS == 0) {
                float v0 = fmaxf(a[0] + bb0, 0.f), v1 = fmaxf(a[1] + bb1, 0.f);
                float v2 = fmaxf(a[2] + bb0, 0.f), v3 = fmaxf(a[3] + bb1, 0.f);
                *(__half2*)(g_H + (size_t)row * D_FF + cg)       = __floats2half2_rn(v0, v1);
                *(__half2*)(g_H + (size_t)(row + 8) * D_FF + cg) = __floats2half2_rn(v2, v3);
            } else {
                int tok0 = g_stok[row], tok1 = g_stok[row + 8];
                if (tok0 >= 0) {
                    float g = g_sgate[row];
                    atomicAdd(out + (size_t)tok0 * D_MODEL + cg,     g * (a[0] + bb0));
                    atomicAdd(out + (size_t)tok0 * D_MODEL + cg + 1, g * (a[1] + bb1));
                }
                if (tok1 >= 0) {
                    float g = g_sgate[row + 8];
                    atomicAdd(out + (size_t)tok1 * D_MODEL + cg,     g * (a[2] + bb0));
                    atomicAdd(out + (size_t)tok1 * D_MODEL + cg + 1, g * (a[3] + bb1));
                }
            }
        }
    }
}

// ---------------------------------------------------------------------------
extern "C" void kernel_launch(void* const* d_in, const int* in_sizes, int n_in,
                              void* d_out, int out_size) {
    const float* x  = (const float*)d_in[0];
    const float* Wr = (const float*)d_in[1];
    const float* W1 = (const float*)d_in[2];
    const float* b1 = (const float*)d_in[3];
    const float* W2 = (const float*)d_in[4];
    const float* b2 = (const float*)d_in[5];
    float* out = (float*)d_out;

    void *pXg, *pW1h, *pW1l, *pW2h, *pW2l, *pH;
    cudaGetSymbolAddress(&pXg,  g_Xg);
    cudaGetSymbolAddress(&pW1h, g_W1T_hi); cudaGetSymbolAddress(&pW1l, g_W1T_lo);
    cudaGetSymbolAddress(&pW2h, g_W2T_hi); cudaGetSymbolAddress(&pW2l, g_W2T_lo);
    cudaGetSymbolAddress(&pH,   g_H);

    cudaFuncSetAttribute(gemm_mma<0>, cudaFuncAttributeMaxDynamicSharedMemorySize, SMEM_GEMM);
    cudaFuncSetAttribute(gemm_mma<1>, cudaFuncAttributeMaxDynamicSharedMemorySize, SMEM_GEMM);

    cudaMemsetAsync(out, 0, (size_t)out_size * sizeof(float));
    zero_counts_kernel<<<1, 32>>>();
    router_kernel<<<T_TOK / 8, 256>>>(x, Wr);
    offsets_kernel<<<1, 1>>>();

    dim3 tb(32, 8);
    transpose_split<<<dim3(D_FF / 32, D_MODEL / 64, N_EXP), tb>>>(
        W1, (__half*)pW1h, (__half*)pW1l, D_MODEL, D_FF);
    transpose_split<<<dim3(D_MODEL / 32, D_FF / 64, N_EXP), tb>>>(
        W2, (__half*)pW2h, (__half*)pW2l, D_FF, D_MODEL);
    gather_x<<<XG_ROWS, 256>>>(x);

    gemm_mma<0><<<dim3(D_FF / 256, MAX_TILES), 512, SMEM_GEMM>>>(
        (const __half*)pXg, (const __half*)pW1h, (const __half*)pW1l, b1, out);
    gemm_mma<1><<<dim3(D_MODEL / 256, MAX_TILES), 512, SMEM_GEMM>>>(
        (const __half*)pH, (const __half*)pW2h, (const __half*)pW2l, b2, out);
}

// round 8
// speedup vs baseline: 5.8131x; 1.6689x over previous
#include <cuda_runtime.h>
#include <cuda_fp16.h>
#include <math.h>
#include <stdint.h>

#define D_MODEL 1024
#define D_FF    4096
#define N_EXP   8
#define T_TOK   4096
#define XG_ROWS 9216          // 8192 + 8*128 padding
#define MAX_TILES 72

// ---- scratch (__device__ globals; no cudaMalloc allowed) --------------------
__device__ int   g_count[N_EXP];
__device__ int   g_off[N_EXP + 1];
__device__ int   g_rows[N_EXP * T_TOK];
__device__ float g_gate[N_EXP * T_TOK];
__device__ int   g_tileE[MAX_TILES];
__device__ int   g_tileM[MAX_TILES];
__device__ int   g_ntiles;
__device__ int   g_stok[XG_ROWS];
__device__ float g_sgate[XG_ROWS];

__device__ __half g_Xg[(size_t)XG_ROWS * D_MODEL];
__device__ __half g_W1T[(size_t)N_EXP * D_FF * D_MODEL];
__device__ __half g_W2T[(size_t)N_EXP * D_MODEL * D_FF];
__device__ __half g_H[(size_t)XG_ROWS * D_FF];

// ---- helpers ----------------------------------------------------------------
#define SWZ(o) ((o) ^ (((o) >> 3) & 0x70))

__device__ __forceinline__ uint32_t smem_u32(const void* p) {
    uint32_t a;
    asm("{ .reg .u64 t; cvta.to.shared.u64 t, %1; cvt.u32.u64 %0, t; }"
        : "=r"(a) : "l"(p));
    return a;
}
__device__ __forceinline__ void cp16(uint32_t dst, const void* src) {
    asm volatile("cp.async.cg.shared.global [%0], [%1], 16;"
                 :: "r"(dst), "l"(src) : "memory");
}
__device__ __forceinline__ void ldsm4(uint32_t* r, uint32_t addr) {
    asm volatile("ldmatrix.sync.aligned.m8n8.x4.shared.b16 {%0,%1,%2,%3}, [%4];"
                 : "=r"(r[0]), "=r"(r[1]), "=r"(r[2]), "=r"(r[3]) : "r"(addr));
}
__device__ __forceinline__ void mma_f16(float* d, const uint32_t* a, const uint32_t* b) {
    asm volatile("mma.sync.aligned.m16n8k16.row.col.f32.f16.f16.f32 "
        "{%0,%1,%2,%3}, {%4,%5,%6,%7}, {%8,%9}, {%0,%1,%2,%3};"
        : "+f"(d[0]), "+f"(d[1]), "+f"(d[2]), "+f"(d[3])
        : "r"(a[0]), "r"(a[1]), "r"(a[2]), "r"(a[3]), "r"(b[0]), "r"(b[1]));
}

// ---- routing ----------------------------------------------------------------
__global__ void zero_counts_kernel() {
    if (threadIdx.x < N_EXP) g_count[threadIdx.x] = 0;
}

__global__ void router_kernel(const float* __restrict__ x,
                              const float* __restrict__ Wr) {
    int tok  = (blockIdx.x * blockDim.x + threadIdx.x) >> 5;
    int lane = threadIdx.x & 31;
    if (tok >= T_TOK) return;
    const float* xr = x + (size_t)tok * D_MODEL;
    float acc[N_EXP];
#pragma unroll
    for (int e = 0; e < N_EXP; e++) acc[e] = 0.f;
    for (int d = lane; d < D_MODEL; d += 32) {
        float xv = xr[d];
        float4 w0 = *(const float4*)(Wr + (size_t)d * N_EXP);
        float4 w1 = *(const float4*)(Wr + (size_t)d * N_EXP + 4);
        acc[0] += xv * w0.x; acc[1] += xv * w0.y;
        acc[2] += xv * w0.z; acc[3] += xv * w0.w;
        acc[4] += xv * w1.x; acc[5] += xv * w1.y;
        acc[6] += xv * w1.z; acc[7] += xv * w1.w;
    }
#pragma unroll
    for (int e = 0; e < N_EXP; e++)
#pragma unroll
        for (int o = 16; o > 0; o >>= 1)
            acc[e] += __shfl_xor_sync(0xffffffffu, acc[e], o);
    if (lane == 0) {
        int e1 = 0; float l1 = acc[0];
#pragma unroll
        for (int e = 1; e < N_EXP; e++)
            if (acc[e] > l1) { l1 = acc[e]; e1 = e; }
        int e2 = (e1 == 0) ? 1 : 0; float l2 = acc[e2];
#pragma unroll
        for (int e = 0; e < N_EXP; e++)
            if (e != e1 && acc[e] > l2) { l2 = acc[e]; e2 = e; }
        float g1 = 1.f / (1.f + expf(l2 - l1));
        float g2 = 1.f - g1;
        int p1 = atomicAdd(&g_count[e1], 1);
        g_rows[e1 * T_TOK + p1] = tok; g_gate[e1 * T_TOK + p1] = g1;
        int p2 = atomicAdd(&g_count[e2], 1);
        g_rows[e2 * T_TOK + p2] = tok; g_gate[e2 * T_TOK + p2] = g2;
    }
}

__global__ void offsets_kernel() {
    if (threadIdx.x != 0) return;
    int s = 0, t = 0;
    for (int e = 0; e < N_EXP; e++) {
        g_off[e] = s;
        int ct = (g_count[e] + 127) >> 7;
        for (int m = 0; m < ct; m++) { g_tileE[t] = e; g_tileM[t] = m << 7; t++; }
        s += ct << 7;
    }
    g_off[N_EXP] = s;
    g_ntiles = t;
}

// gather tokens to padded layout; fp32 -> fp16; zero pad rows
__global__ void gather_x(const float* __restrict__ x) {
    int r = blockIdx.x;
    if (r >= g_off[N_EXP]) return;
    int e = 0;
#pragma unroll
    for (int k = 1; k < N_EXP; k++) if (r >= g_off[k]) e = k;
    int i = r - g_off[e];
    int tok = (i < g_count[e]) ? g_rows[e * T_TOK + i] : -1;
    if (threadIdx.x == 0) {
        g_stok[r]  = tok;
        g_sgate[r] = (tok >= 0) ? g_gate[e * T_TOK + i] : 0.f;
    }
    size_t base = (size_t)r * D_MODEL;
    if (tok < 0) {
        __half2 z = __floats2half2_rn(0.f, 0.f);
        for (int c = threadIdx.x; c < D_MODEL / 2; c += blockDim.x)
            *(__half2*)(g_Xg + base + 2 * c) = z;
        return;
    }
    const float2* xp = (const float2*)(x + (size_t)tok * D_MODEL);
    for (int c = threadIdx.x; c < D_MODEL / 2; c += blockDim.x) {
        float2 v = xp[c];
        *(__half2*)(g_Xg + base + 2 * c) = __floats2half2_rn(v.x, v.y);
    }
}

// transpose: W[e][K][N] fp32 -> WT[e][N][K] fp16
__global__ void transpose_half(const float* __restrict__ W,
                               __half* __restrict__ dst,
                               int K, int N) {
    __shared__ float t[64][33];
    int e  = blockIdx.z;
    int k0 = blockIdx.y * 64, n0 = blockIdx.x * 32;
    int tx = threadIdx.x, ty = threadIdx.y;
    const float* Wp = W + ((size_t)e * K + k0) * N + n0;
#pragma unroll
    for (int i = ty; i < 64; i += 8)
        t[i][tx] = Wp[(size_t)i * N + tx];
    __syncthreads();
    size_t base = ((size_t)e * N + n0) * K + k0;
#pragma unroll
    for (int j = ty; j < 32; j += 8) {
        float v0 = t[2 * tx][j], v1 = t[2 * tx + 1][j];
        *(__half2*)(dst + base + (size_t)j * K + 2 * tx) = __floats2half2_rn(v0, v1);
    }
}

// ---------------------------------------------------------------------------
// fp16 mma.sync GEMM: 128x256 CTA tile, 512 threads, BK=64, 2-stage cp.async.
// Single fp16 digit both sides: 1 MMA per (k16, subtile).
// Stage (48 KB): A 16K | B 32K
static constexpr int STG_BYTES = 49152;
static constexpr int SMEM_GEMM = 2 * STG_BYTES;

#define LOAD_STAGE(s, ktile) do {                                              \
    uint32_t st_ = sb + (uint32_t)(s) * STG_BYTES;                             \
    int k0_ = (ktile) * 64;                                                    \
    _Pragma("unroll")                                                          \
    for (int i_ = 0; i_ < 2; i_++) {                                           \
        int idx_ = tid + i_ * 512;                                             \
        int r_ = idx_ >> 3, cb_ = (idx_ & 7) << 4;                             \
        uint32_t sw_ = SWZ(r_ * 128 + cb_);                                    \
        size_t ga_ = ((size_t)(rowA0 + r_) * KTOT + k0_) * 2 + cb_;            \
        cp16(st_ + sw_, (const char*)Ax + ga_);                                \
    }                                                                          \
    _Pragma("unroll")                                                          \
    for (int i_ = 0; i_ < 4; i_++) {                                           \
        int idx_ = tid + i_ * 512;                                             \
        int r_ = idx_ >> 3, cb_ = (idx_ & 7) << 4;                             \
        uint32_t sw_ = SWZ(r_ * 128 + cb_);                                    \
        size_t gb_ = ((size_t)(bRow0 + r_) * KTOT + k0_) * 2 + cb_;            \
        cp16(st_ + 16384 + sw_, (const char*)Bx + gb_);                        \
    }                                                                          \
    asm volatile("cp.async.commit_group;" ::: "memory");                       \
} while (0)

template<int PASS>
__global__ void __launch_bounds__(512, 1)
gemm_mma(const __half* __restrict__ Ax, const __half* __restrict__ Bx,
         const float* __restrict__ bias, float* __restrict__ out)
{
    constexpr int KTOT = (PASS == 0) ? D_MODEL : D_FF;
    constexpr int NTOT = (PASS == 0) ? D_FF : D_MODEL;
    constexpr int KIT  = KTOT / 64;

    int t = blockIdx.y;
    if (t >= g_ntiles) return;
    int e     = g_tileE[t];
    int rowA0 = g_off[e] + g_tileM[t];
    int n0    = blockIdx.x * 256;
    int bRow0 = e * NTOT + n0;

    extern __shared__ char smem[];
    uint32_t sb = smem_u32(smem);

    int tid = threadIdx.x;
    int wid = tid >> 5, lane = tid & 31;
    int wm = wid >> 3, wn = wid & 7;       // warp tile: rows wm*64, cols wn*32

    float acc[4][4][4];
#pragma unroll
    for (int a = 0; a < 4; a++)
#pragma unroll
        for (int b = 0; b < 4; b++)
#pragma unroll
            for (int c = 0; c < 4; c++) acc[a][b][c] = 0.f;

    LOAD_STAGE(0, 0);
    LOAD_STAGE(1, 1);

    for (int kt = 0; kt < KIT; kt++) {
        if (kt + 1 < KIT) asm volatile("cp.async.wait_group 1;" ::: "memory");
        else              asm volatile("cp.async.wait_group 0;" ::: "memory");
        __syncthreads();
        uint32_t sA = sb + (uint32_t)(kt & 1) * STG_BYTES;
        uint32_t sB = sA + 16384;
#pragma unroll
        for (int k16 = 0; k16 < 4; k16++) {
            uint32_t b_f[2][4];
#pragma unroll
            for (int nt = 0; nt < 2; nt++) {
                uint32_t bd = sB + SWZ((wn * 32 + nt * 16 + (lane & 15)) * 128
                                       + k16 * 32 + (lane >> 4) * 16);
                ldsm4(b_f[nt], bd);
            }
#pragma unroll
            for (int mt = 0; mt < 4; mt++) {
                uint32_t a_f[4];
                uint32_t ad = sA + SWZ((wm * 64 + mt * 16 + (lane & 15)) * 128
                                       + k16 * 32 + (lane >> 4) * 16);
                ldsm4(a_f, ad);
#pragma unroll
                for (int n8 = 0; n8 < 4; n8++) {
                    int nt = n8 >> 1, hf = n8 & 1;
                    uint32_t bb[2] = { b_f[nt][hf], b_f[nt][2 + hf] };
                    mma_f16(acc[mt][n8], a_f, bb);
                }
            }
        }
        __syncthreads();
        if (kt + 2 < KIT) { LOAD_STAGE(kt & 1, kt + 2); }
    }

    // ---- epilogue ----
    const float* bp = bias + (size_t)e * NTOT;
#pragma unroll
    for (int mt = 0; mt < 4; mt++) {
        int r0 = wm * 64 + mt * 16 + (lane >> 2);
#pragma unroll
        for (int n8 = 0; n8 < 4; n8++) {
            int cg = n0 + wn * 32 + n8 * 8 + (lane & 3) * 2;
            float* a = acc[mt][n8];
            float bb0 = bp[cg], bb1 = bp[cg + 1];
            int row = rowA0 + r0;
            if (PASS == 0) {
                float v0 = fmaxf(a[0] + bb0, 0.f), v1 = fmaxf(a[1] + bb1, 0.f);
                float v2 = fmaxf(a[2] + bb0, 0.f), v3 = fmaxf(a[3] + bb1, 0.f);
                *(__half2*)(g_H + (size_t)row * D_FF + cg)       = __floats2half2_rn(v0, v1);
                *(__half2*)(g_H + (size_t)(row + 8) * D_FF + cg) = __floats2half2_rn(v2, v3);
            } else {
                int tok0 = g_stok[row], tok1 = g_stok[row + 8];
                if (tok0 >= 0) {
                    float g = g_sgate[row];
                    atomicAdd(out + (size_t)tok0 * D_MODEL + cg,     g * (a[0] + bb0));
                    atomicAdd(out + (size_t)tok0 * D_MODEL + cg + 1, g * (a[1] + bb1));
                }
                if (tok1 >= 0) {
                    float g = g_sgate[row + 8];
                    atomicAdd(out + (size_t)tok1 * D_MODEL + cg,     g * (a[2] + bb0));
                    atomicAdd(out + (size_t)tok1 * D_MODEL + cg + 1, g * (a[3] + bb1));
                }
            }
        }
    }
}

// ---------------------------------------------------------------------------
extern "C" void kernel_launch(void* const* d_in, const int* in_sizes, int n_in,
                              void* d_out, int out_size) {
    const float* x  = (const float*)d_in[0];
    const float* Wr = (const float*)d_in[1];
    const float* W1 = (const float*)d_in[2];
    const float* b1 = (const float*)d_in[3];
    const float* W2 = (const float*)d_in[4];
    const float* b2 = (const float*)d_in[5];
    float* out = (float*)d_out;

    void *pXg, *pW1, *pW2, *pH;
    cudaGetSymbolAddress(&pXg, g_Xg);
    cudaGetSymbolAddress(&pW1, g_W1T);
    cudaGetSymbolAddress(&pW2, g_W2T);
    cudaGetSymbolAddress(&pH,  g_H);

    cudaFuncSetAttribute(gemm_mma<0>, cudaFuncAttributeMaxDynamicSharedMemorySize, SMEM_GEMM);
    cudaFuncSetAttribute(gemm_mma<1>, cudaFuncAttributeMaxDynamicSharedMemorySize, SMEM_GEMM);

    cudaMemsetAsync(out, 0, (size_t)out_size * sizeof(float));
    zero_counts_kernel<<<1, 32>>>();
    router_kernel<<<T_TOK / 8, 256>>>(x, Wr);
    offsets_kernel<<<1, 1>>>();

    dim3 tb(32, 8);
    transpose_half<<<dim3(D_FF / 32, D_MODEL / 64, N_EXP), tb>>>(W1, (__half*)pW1, D_MODEL, D_FF);
    transpose_half<<<dim3(D_MODEL / 32, D_FF / 64, N_EXP), tb>>>(W2, (__half*)pW2, D_FF, D_MODEL);
    gather_x<<<XG_ROWS, 256>>>(x);

    gemm_mma<0><<<dim3(D_FF / 256, MAX_TILES), 512, SMEM_GEMM>>>(
        (const __half*)pXg, (const __half*)pW1, b1, out);
    gemm_mma<1><<<dim3(D_MODEL / 256, MAX_TILES), 512, SMEM_GEMM>>>(
        (const __half*)pH, (const __half*)pW2, b2, out);
}

// round 9
// speedup vs baseline: 6.7976x; 1.1694x over previous
#include <cuda_runtime.h>
#include <cuda_fp16.h>
#include <math.h>
#include <stdint.h>

#define D_MODEL 1024
#define D_FF    4096
#define N_EXP   8
#define T_TOK   4096
#define XG_ROWS 9216
#define MAX_TILES 72

// ---- scratch (__device__ globals; no cudaMalloc allowed) --------------------
__device__ int   g_count[N_EXP];
__device__ int   g_off[N_EXP + 1];
__device__ int   g_rows[N_EXP * T_TOK];
__device__ float g_gate[N_EXP * T_TOK];
__device__ int   g_tileE[MAX_TILES];
__device__ int   g_tileM[MAX_TILES];
__device__ int   g_ntiles;
__device__ int   g_stok[XG_ROWS];
__device__ float g_sgate[XG_ROWS];

__device__ __half g_Xh[(size_t)T_TOK * D_MODEL];               // x in fp16, natural layout
__device__ __half g_W1h[(size_t)N_EXP * D_MODEL * D_FF];       // [E][K][N] fp16 (no transpose)
__device__ __half g_W2h[(size_t)N_EXP * D_FF * D_MODEL];       // [E][K][N] fp16
__device__ __half g_H[(size_t)XG_ROWS * D_FF];                 // padded gathered H

// ---- helpers ----------------------------------------------------------------
#define SWZ(o) ((o) ^ (((o) >> 3) & 0x70))

__device__ __forceinline__ uint32_t smem_u32(const void* p) {
    uint32_t a;
    asm("{ .reg .u64 t; cvta.to.shared.u64 t, %1; cvt.u32.u64 %0, t; }"
        : "=r"(a) : "l"(p));
    return a;
}
__device__ __forceinline__ void cp16(uint32_t dst, const void* src) {
    asm volatile("cp.async.cg.shared.global [%0], [%1], 16;"
                 :: "r"(dst), "l"(src) : "memory");
}
// zero-fills when n < 16 (n = 0 for pad rows)
__device__ __forceinline__ void cp16z(uint32_t dst, const void* src, uint32_t n) {
    asm volatile("cp.async.cg.shared.global [%0], [%1], 16, %2;"
                 :: "r"(dst), "l"(src), "r"(n) : "memory");
}
__device__ __forceinline__ void ldsm4(uint32_t* r, uint32_t addr) {
    asm volatile("ldmatrix.sync.aligned.m8n8.x4.shared.b16 {%0,%1,%2,%3}, [%4];"
                 : "=r"(r[0]), "=r"(r[1]), "=r"(r[2]), "=r"(r[3]) : "r"(addr));
}
__device__ __forceinline__ void ldsm4t(uint32_t* r, uint32_t addr) {
    asm volatile("ldmatrix.sync.aligned.m8n8.x4.trans.shared.b16 {%0,%1,%2,%3}, [%4];"
                 : "=r"(r[0]), "=r"(r[1]), "=r"(r[2]), "=r"(r[3]) : "r"(addr));
}
__device__ __forceinline__ void mma_f16(float* d, const uint32_t* a, const uint32_t* b) {
    asm volatile("mma.sync.aligned.m16n8k16.row.col.f32.f16.f16.f32 "
        "{%0,%1,%2,%3}, {%4,%5,%6,%7}, {%8,%9}, {%0,%1,%2,%3};"
        : "+f"(d[0]), "+f"(d[1]), "+f"(d[2]), "+f"(d[3])
        : "r"(a[0]), "r"(a[1]), "r"(a[2]), "r"(a[3]), "r"(b[0]), "r"(b[1]));
}

// ---- streaming fp32 -> fp16 (8 elems / thread) -------------------------------
__global__ void f32_to_f16(const float* __restrict__ s, __half* __restrict__ d) {
    size_t i = ((size_t)blockIdx.x * blockDim.x + threadIdx.x) * 8;
    float4 a = *(const float4*)(s + i);
    float4 b = *(const float4*)(s + i + 4);
    __half2 h[4] = { __floats2half2_rn(a.x, a.y), __floats2half2_rn(a.z, a.w),
                     __floats2half2_rn(b.x, b.y), __floats2half2_rn(b.z, b.w) };
    *(uint4*)(d + i) = *(uint4*)h;
}

// ---- routing ----------------------------------------------------------------
__global__ void zero_counts_kernel() {
    if (threadIdx.x < N_EXP) g_count[threadIdx.x] = 0;
}

__global__ void router_kernel(const float* __restrict__ x,
                              const float* __restrict__ Wr) {
    int tok  = (blockIdx.x * blockDim.x + threadIdx.x) >> 5;
    int lane = threadIdx.x & 31;
    if (tok >= T_TOK) return;
    const float* xr = x + (size_t)tok * D_MODEL;
    float acc[N_EXP];
#pragma unroll
    for (int e = 0; e < N_EXP; e++) acc[e] = 0.f;
    for (int d = lane; d < D_MODEL; d += 32) {
        float xv = xr[d];
        float4 w0 = *(const float4*)(Wr + (size_t)d * N_EXP);
        float4 w1 = *(const float4*)(Wr + (size_t)d * N_EXP + 4);
        acc[0] += xv * w0.x; acc[1] += xv * w0.y;
        acc[2] += xv * w0.z; acc[3] += xv * w0.w;
        acc[4] += xv * w1.x; acc[5] += xv * w1.y;
        acc[6] += xv * w1.z; acc[7] += xv * w1.w;
    }
#pragma unroll
    for (int e = 0; e < N_EXP; e++)
#pragma unroll
        for (int o = 16; o > 0; o >>= 1)
            acc[e] += __shfl_xor_sync(0xffffffffu, acc[e], o);
    if (lane == 0) {
        int e1 = 0; float l1 = acc[0];
#pragma unroll
        for (int e = 1; e < N_EXP; e++)
            if (acc[e] > l1) { l1 = acc[e]; e1 = e; }
        int e2 = (e1 == 0) ? 1 : 0; float l2 = acc[e2];
#pragma unroll
        for (int e = 0; e < N_EXP; e++)
            if (e != e1 && acc[e] > l2) { l2 = acc[e]; e2 = e; }
        float g1 = 1.f / (1.f + expf(l2 - l1));
        float g2 = 1.f - g1;
        int p1 = atomicAdd(&g_count[e1], 1);
        g_rows[e1 * T_TOK + p1] = tok; g_gate[e1 * T_TOK + p1] = g1;
        int p2 = atomicAdd(&g_count[e2], 1);
        g_rows[e2 * T_TOK + p2] = tok; g_gate[e2 * T_TOK + p2] = g2;
    }
}

__global__ void offsets_kernel() {
    if (threadIdx.x != 0) return;
    int s = 0, t = 0;
    for (int e = 0; e < N_EXP; e++) {
        g_off[e] = s;
        int ct = (g_count[e] + 127) >> 7;
        for (int m = 0; m < ct; m++) { g_tileE[t] = e; g_tileM[t] = m << 7; t++; }
        s += ct << 7;
    }
    g_off[N_EXP] = s;
    g_ntiles = t;
}

// per-slot metadata: slot -> (token, gate)
__global__ void slot_meta() {
    int r = blockIdx.x * 256 + threadIdx.x;
    if (r >= XG_ROWS) return;
    int e = 0;
#pragma unroll
    for (int k = 1; k < N_EXP; k++) if (r >= g_off[k]) e = k;
    int i = r - g_off[e];
    int tok = (r < g_off[N_EXP] && i < g_count[e]) ? g_rows[e * T_TOK + i] : -1;
    g_stok[r]  = tok;
    g_sgate[r] = (tok >= 0) ? g_gate[e * T_TOK + i] : 0.f;
}

// ---------------------------------------------------------------------------
// fp16 mma.sync GEMM: 128x256 CTA tile, 512 threads, BK=64, 2-stage cp.async.
// A: K-major rows (gathered / H), SW128 swizzle, non-trans ldmatrix.
// B: row-major [K][N] weights, 512B rows with chunk^(row&7) swizzle, trans ldmatrix.
// Stage (48 KB): A 16K | B 32K
static constexpr int STG_BYTES = 49152;
static constexpr int SMEM_GEMM = 2 * STG_BYTES;

#define LOAD_STAGE(s, ktile) do {                                              \
    uint32_t st_ = sb + (uint32_t)(s) * STG_BYTES;                             \
    size_t koffA_ = (size_t)(ktile) * 128;        /* 64 elems * 2B */          \
    size_t koffB_ = (size_t)(ktile) * 64 * NTOT * 2;                           \
    cp16z(st_ + aphys0, asrc0 + koffA_, asz0);                                 \
    cp16z(st_ + aphys1, asrc1 + koffA_, asz1);                                 \
    _Pragma("unroll")                                                          \
    for (int i_ = 0; i_ < 4; i_++) {                                           \
        cp16(st_ + 16384 + bphys + (uint32_t)i_ * (16 * 512),                  \
             bsrc + koffB_ + (size_t)i_ * 16 * NTOT * 2);                      \
    }                                                                          \
    asm volatile("cp.async.commit_group;" ::: "memory");                       \
} while (0)

template<int PASS>
__global__ void __launch_bounds__(512, 1)
gemm_mma(const __half* __restrict__ Ax, const __half* __restrict__ Bx,
         const float* __restrict__ bias, float* __restrict__ out)
{
    constexpr int KTOT = (PASS == 0) ? D_MODEL : D_FF;
    constexpr int NTOT = (PASS == 0) ? D_FF : D_MODEL;
    constexpr int KIT  = KTOT / 64;

    int t = blockIdx.y;
    if (t >= g_ntiles) return;
    int e     = g_tileE[t];
    int rowA0 = g_off[e] + g_tileM[t];
    int n0    = blockIdx.x * 256;

    extern __shared__ char smem[];
    uint32_t sb = smem_u32(smem);

    int tid = threadIdx.x;
    int wid = tid >> 5, lane = tid & 31;
    int wm = wid >> 3, wn = wid & 7;       // warp tile: rows wm*64, cols wn*32

    // ---- producer address precompute ----
    // A: thread owns rows (tid>>3) and (tid>>3)+64, chunk (tid&7)*16 bytes
    int ar0 = tid >> 3, ar1 = ar0 + 64;
    uint32_t acb = (tid & 7) << 4;
    uint32_t aphys0 = SWZ(ar0 * 128 + acb);
    uint32_t aphys1 = SWZ(ar1 * 128 + acb);
    const char* asrc0; const char* asrc1;
    uint32_t asz0 = 16, asz1 = 16;
    if (PASS == 0) {
        int t0 = g_stok[rowA0 + ar0], t1 = g_stok[rowA0 + ar1];
        asz0 = (t0 >= 0) ? 16u : 0u;  asz1 = (t1 >= 0) ? 16u : 0u;
        asrc0 = (const char*)Ax + ((size_t)max(t0, 0) * KTOT) * 2 + acb;
        asrc1 = (const char*)Ax + ((size_t)max(t1, 0) * KTOT) * 2 + acb;
    } else {
        asrc0 = (const char*)Ax + ((size_t)(rowA0 + ar0) * KTOT) * 2 + acb;
        asrc1 = (const char*)Ax + ((size_t)(rowA0 + ar1) * KTOT) * 2 + acb;
    }
    // B: thread owns k-rows (tid>>5)+16i, chunk (tid&31)
    int br = tid >> 5, bc = tid & 31;
    uint32_t bphys = (uint32_t)br * 512 + (uint32_t)((bc ^ (br & 7)) << 4);
    const char* bsrc = (const char*)Bx
        + ((size_t)(e * KTOT + br) * NTOT + n0) * 2 + (size_t)bc * 16;

    // ---- consumer fragment address precompute (B trans) ----
    int krb = (lane & 7) + ((lane >> 4) << 3);          // 0..15 within k16
    int nc  = (lane >> 3) & 1;                           // n-chunk offset 0/1
    uint32_t bck[2];
    bck[0] = (uint32_t)(((wn * 4 + 0 + nc) ^ (lane & 7)) << 4);
    bck[1] = (uint32_t)(((wn * 4 + 2 + nc) ^ (lane & 7)) << 4);

    float acc[4][4][4];
#pragma unroll
    for (int a = 0; a < 4; a++)
#pragma unroll
        for (int b = 0; b < 4; b++)
#pragma unroll
            for (int c = 0; c < 4; c++) acc[a][b][c] = 0.f;

    LOAD_STAGE(0, 0);
    LOAD_STAGE(1, 1);

    for (int kt = 0; kt < KIT; kt++) {
        if (kt + 1 < KIT) asm volatile("cp.async.wait_group 1;" ::: "memory");
        else              asm volatile("cp.async.wait_group 0;" ::: "memory");
        __syncthreads();
        uint32_t sA = sb + (uint32_t)(kt & 1) * STG_BYTES;
        uint32_t sB = sA + 16384;
#pragma unroll
        for (int k16 = 0; k16 < 4; k16++) {
            uint32_t b_f[2][4];
            uint32_t krow = (uint32_t)(k16 * 16 + krb) * 512;
#pragma unroll
            for (int nt = 0; nt < 2; nt++)
                ldsm4t(b_f[nt], sB + krow + bck[nt]);
#pragma unroll
            for (int mt = 0; mt < 4; mt++) {
                uint32_t a_f[4];
                uint32_t ad = sA + SWZ((wm * 64 + mt * 16 + (lane & 15)) * 128
                                       + k16 * 32 + (lane >> 4) * 16);
                ldsm4(a_f, ad);
#pragma unroll
                for (int n8 = 0; n8 < 4; n8++) {
                    int nt = n8 >> 1, hf = n8 & 1;
                    uint32_t bb[2] = { b_f[nt][hf], b_f[nt][2 + hf] };
                    mma_f16(acc[mt][n8], a_f, bb);
                }
            }
        }
        __syncthreads();
        if (kt + 2 < KIT) { LOAD_STAGE(kt & 1, kt + 2); }
    }

    // ---- epilogue ----
    const float* bp = bias + (size_t)e * NTOT;
#pragma unroll
    for (int mt = 0; mt < 4; mt++) {
        int r0 = wm * 64 + mt * 16 + (lane >> 2);
#pragma unroll
        for (int n8 = 0; n8 < 4; n8++) {
            int cg = n0 + wn * 32 + n8 * 8 + (lane & 3) * 2;
            float* a = acc[mt][n8];
            float bb0 = bp[cg], bb1 = bp[cg + 1];
            int row = rowA0 + r0;
            if (PASS == 0) {
                float v0 = fmaxf(a[0] + bb0, 0.f), v1 = fmaxf(a[1] + bb1, 0.f);
                float v2 = fmaxf(a[2] + bb0, 0.f), v3 = fmaxf(a[3] + bb1, 0.f);
                *(__half2*)(g_H + (size_t)row * D_FF + cg)       = __floats2half2_rn(v0, v1);
                *(__half2*)(g_H + (size_t)(row + 8) * D_FF + cg) = __floats2half2_rn(v2, v3);
            } else {
                int tok0 = g_stok[row], tok1 = g_stok[row + 8];
                if (tok0 >= 0) {
                    float g = g_sgate[row];
                    atomicAdd(out + (size_t)tok0 * D_MODEL + cg,     g * (a[0] + bb0));
                    atomicAdd(out + (size_t)tok0 * D_MODEL + cg + 1, g * (a[1] + bb1));
                }
                if (tok1 >= 0) {
                    float g = g_sgate[row + 8];
                    atomicAdd(out + (size_t)tok1 * D_MODEL + cg,     g * (a[2] + bb0));
                    atomicAdd(out + (size_t)tok1 * D_MODEL + cg + 1, g * (a[3] + bb1));
                }
            }
        }
    }
}

// ---------------------------------------------------------------------------
extern "C" void kernel_launch(void* const* d_in, const int* in_sizes, int n_in,
                              void* d_out, int out_size) {
    const float* x  = (const float*)d_in[0];
    const float* Wr = (const float*)d_in[1];
    const float* W1 = (const float*)d_in[2];
    const float* b1 = (const float*)d_in[3];
    const float* W2 = (const float*)d_in[4];
    const float* b2 = (const float*)d_in[5];
    float* out = (float*)d_out;

    void *pXh, *pW1, *pW2, *pH;
    cudaGetSymbolAddress(&pXh, g_Xh);
    cudaGetSymbolAddress(&pW1, g_W1h);
    cudaGetSymbolAddress(&pW2, g_W2h);
    cudaGetSymbolAddress(&pH,  g_H);

    cudaFuncSetAttribute(gemm_mma<0>, cudaFuncAttributeMaxDynamicSharedMemorySize, SMEM_GEMM);
    cudaFuncSetAttribute(gemm_mma<1>, cudaFuncAttributeMaxDynamicSharedMemorySize, SMEM_GEMM);

    cudaMemsetAsync(out, 0, (size_t)out_size * sizeof(float));
    zero_counts_kernel<<<1, 32>>>();
    router_kernel<<<T_TOK / 8, 256>>>(x, Wr);
    offsets_kernel<<<1, 1>>>();
    slot_meta<<<XG_ROWS / 256, 256>>>();

    // streaming fp32 -> fp16 converts (no transpose needed)
    f32_to_f16<<<(int)(((size_t)N_EXP * D_MODEL * D_FF) / 8 / 256), 256>>>(W1, (__half*)pW1);
    f32_to_f16<<<(int)(((size_t)N_EXP * D_FF * D_MODEL) / 8 / 256), 256>>>(W2, (__half*)pW2);
    f32_to_f16<<<(int)(((size_t)T_TOK * D_MODEL) / 8 / 256), 256>>>(x, (__half*)pXh);

    gemm_mma<0><<<dim3(D_FF / 256, MAX_TILES), 512, SMEM_GEMM>>>(
        (const __half*)pXh, (const __half*)pW1, b1, out);
    gemm_mma<1><<<dim3(D_MODEL / 256, MAX_TILES), 512, SMEM_GEMM>>>(
        (const __half*)pH, (const __half*)pW2, b2, out);
}